// round 6
// baseline (speedup 1.0000x reference)
#include <cuda_runtime.h>
#include <cuda_bf16.h>

#define NN   50000
#define EE   800000
#define HH   8
#define CPHN 16
#define NEG  0.2f
#define EPSN 1e-5f

// Scratch (device globals; allocation-free rule)
__device__ __align__(16) float g_xw[NN * 256];   // [n][hop*128 + h*16 + c]
__device__ __align__(16) float g_att[NN * 32];   // [n][hop*16 + {as:0..7, ad:8..15}]
__device__ __align__(16) float g_s[NN * 16];     // softmax denominator partial (edges only)
__device__ __align__(16) float g_acc[NN * 256];  // unnormalized weighted sums (edges only)

__device__ __forceinline__ float lrelu(float v) { return v > 0.f ? v : NEG * v; }

// ---------------------------------------------------------------------------
// 1) xw = x @ [W0 | W1]  -> g_xw [NN, 256]
// 64x64 tile, BK=16, 4x4 microtile, 256 threads
// ---------------------------------------------------------------------------
__global__ __launch_bounds__(256) void gemm_kernel(const float* __restrict__ A,
                                                   const float* __restrict__ W0,
                                                   const float* __restrict__ W1) {
    __shared__ __align__(16) float As[16][72];
    __shared__ __align__(16) float Bs[16][72];
    const int bm = blockIdx.y * 64;
    const int bn = blockIdx.x * 64;                 // 0,64,128,192
    const float* W = (bn < 128) ? W0 : W1;
    const int wcol = bn & 127;
    const int tid = threadIdx.x;
    const int ty = tid >> 4, tx = tid & 15;

    float acc[4][4] = {};
    const int arow = tid >> 2, ak4 = (tid & 3) * 4; // A loader mapping
    const int bk = tid >> 4, bn4 = (tid & 15) * 4;  // B loader mapping

    for (int k0 = 0; k0 < 256; k0 += 16) {
        float4 av = make_float4(0.f, 0.f, 0.f, 0.f);
        const int grow = bm + arow;
        if (grow < NN) av = *(const float4*)&A[grow * 256 + k0 + ak4];
        As[ak4 + 0][arow] = av.x;
        As[ak4 + 1][arow] = av.y;
        As[ak4 + 2][arow] = av.z;
        As[ak4 + 3][arow] = av.w;
        *(float4*)&Bs[bk][bn4] = *(const float4*)&W[(k0 + bk) * 128 + wcol + bn4];
        __syncthreads();
#pragma unroll
        for (int k = 0; k < 16; k++) {
            float4 a4 = *(const float4*)&As[k][ty * 4];
            float4 b4 = *(const float4*)&Bs[k][tx * 4];
            float a[4] = {a4.x, a4.y, a4.z, a4.w};
            float b[4] = {b4.x, b4.y, b4.z, b4.w};
#pragma unroll
            for (int i = 0; i < 4; i++)
#pragma unroll
                for (int j = 0; j < 4; j++) acc[i][j] += a[i] * b[j];
        }
        __syncthreads();
    }
#pragma unroll
    for (int i = 0; i < 4; i++) {
        const int grow = bm + ty * 4 + i;
        if (grow < NN) {
            float4 v = make_float4(acc[i][0], acc[i][1], acc[i][2], acc[i][3]);
            *(float4*)&g_xw[grow * 256 + bn + tx * 4] = v;
        }
    }
}

// ---------------------------------------------------------------------------
// 2) per-(node,head): attention logit pieces a_s, a_d for both hops
// ---------------------------------------------------------------------------
__global__ __launch_bounds__(256) void att_init_kernel(const float* __restrict__ as0,
                                                       const float* __restrict__ ad0,
                                                       const float* __restrict__ as1,
                                                       const float* __restrict__ ad1) {
    int t = blockIdx.x * blockDim.x + threadIdx.x;
    if (t >= NN * HH) return;
    const int n = t >> 3, h = t & 7;
    const float* xw0 = &g_xw[n * 256 + h * CPHN];
    const float* xw1 = xw0 + 128;
    float s0 = 0.f, d0 = 0.f, s1 = 0.f, d1 = 0.f;
#pragma unroll
    for (int c = 0; c < CPHN; c++) {
        const float v0 = xw0[c], v1 = xw1[c];
        s0 += v0 * __ldg(&as0[h * CPHN + c]);
        d0 += v0 * __ldg(&ad0[h * CPHN + c]);
        s1 += v1 * __ldg(&as1[h * CPHN + c]);
        d1 += v1 * __ldg(&ad1[h * CPHN + c]);
    }
    g_att[n * 32 + h]      = s0;
    g_att[n * 32 + 8 + h]  = d0;
    g_att[n * 32 + 16 + h] = s1;
    g_att[n * 32 + 24 + h] = d1;
}

__global__ void zero_kernel() {
    const int idx = blockIdx.x * blockDim.x + threadIdx.x;
    const int stride = gridDim.x * blockDim.x;
    const float4 z = make_float4(0.f, 0.f, 0.f, 0.f);
    for (int i = idx; i < NN * 16 / 4; i += stride) ((float4*)g_s)[i] = z;
    for (int i = idx; i < NN * 256 / 4; i += stride) ((float4*)g_acc)[i] = z;
}

// ---------------------------------------------------------------------------
// 3) edge pass: p = exp(e); accumulate denom + p*xw[src]  (warp per edge)
//    (softmax is shift-invariant; logits are O(1) so no max subtraction needed)
// ---------------------------------------------------------------------------
template <int HOP>
__global__ __launch_bounds__(256) void edge_acc_kernel(const int* __restrict__ row,
                                                       const int* __restrict__ col) {
    const int w = (blockIdx.x * blockDim.x + threadIdx.x) >> 5;
    const int lane = threadIdx.x & 31;
    if (w >= EE) return;
    int s, d;
    if (HOP == 0) {
        s = __ldg(&row[w]);
        d = __ldg(&col[w]);
    } else {
        const int c = __ldg(&col[w]);
        s = __ldg(&row[c]);
        d = __ldg(&col[c]);
    }
    float p = 0.f;
    if (lane < 8) {
        const float as_ = g_att[s * 32 + HOP * 16 + lane];
        const float ad_ = g_att[d * 32 + HOP * 16 + 8 + lane];
        p = __expf(lrelu(as_ + ad_));
        atomicAdd(&g_s[d * 16 + HOP * 8 + lane], p);
    }
    const int h0 = lane >> 4;  // channel j=lane+32i -> head = h0 + 2i
    const float p0 = __shfl_sync(0xffffffffu, p, h0);
    const float p1 = __shfl_sync(0xffffffffu, p, h0 + 2);
    const float p2 = __shfl_sync(0xffffffffu, p, h0 + 4);
    const float p3 = __shfl_sync(0xffffffffu, p, h0 + 6);
    const float* xs = &g_xw[s * 256 + HOP * 128];
    float* ac = &g_acc[d * 256 + HOP * 128];
    atomicAdd(&ac[lane], p0 * xs[lane]);
    atomicAdd(&ac[lane + 32], p1 * xs[lane + 32]);
    atomicAdd(&ac[lane + 64], p2 * xs[lane + 64]);
    atomicAdd(&ac[lane + 96], p3 * xs[lane + 96]);
}

// ---------------------------------------------------------------------------
// 4) finalize: fold self loop(s), normalize, bias, residual, LayerNorm (warp/node)
//    Hop-2 self loops appear TWICE in the reference (explicit concat + the one
//    _gat_conv adds), so the self term is doubled for hop 1.
// ---------------------------------------------------------------------------
__global__ __launch_bounds__(256) void finalize_kernel(const float* __restrict__ x,
                                                       const float* __restrict__ b0,
                                                       const float* __restrict__ b1,
                                                       const float* __restrict__ gamma,
                                                       const float* __restrict__ beta,
                                                       float* __restrict__ out) {
    const int n = (blockIdx.x * blockDim.x + threadIdx.x) >> 5;
    const int lane = threadIdx.x & 31;
    if (n >= NN) return;
    float p = 0.f, stot = 1.f;
    if (lane < 16) {  // slot = hop*8 + h = lane
        const int hop = lane >> 3, h = lane & 7;
        const float as_ = g_att[n * 32 + hop * 16 + h];
        const float ad_ = g_att[n * 32 + hop * 16 + 8 + h];
        const float mult = (hop == 0) ? 1.f : 2.f;   // hop-2 self loop counted twice
        p = mult * __expf(lrelu(as_ + ad_));         // self-loop contribution
        stot = g_s[n * 16 + lane] + p;
    }
    float vals[8];
    float sum = 0.f, sumsq = 0.f;
#pragma unroll
    for (int i = 0; i < 8; i++) {
        const int j = lane + 32 * i;
        const int slot = j >> 4;  // = hop*8 + head
        const float pj = __shfl_sync(0xffffffffu, p, slot);
        const float sj = __shfl_sync(0xffffffffu, stot, slot);
        const float bias = (j < 128) ? __ldg(&b0[j]) : __ldg(&b1[j - 128]);
        const float v =
            (g_acc[n * 256 + j] + pj * g_xw[n * 256 + j]) / sj + bias + x[n * 256 + j];
        vals[i] = v;
        sum += v;
        sumsq += v * v;
    }
#pragma unroll
    for (int o = 16; o > 0; o >>= 1) {
        sum += __shfl_xor_sync(0xffffffffu, sum, o);
        sumsq += __shfl_xor_sync(0xffffffffu, sumsq, o);
    }
    const float mu = sum * (1.f / 256.f);
    const float var = sumsq * (1.f / 256.f) - mu * mu;
    const float inv = rsqrtf(var + EPSN);
#pragma unroll
    for (int i = 0; i < 8; i++) {
        const int j = lane + 32 * i;
        out[n * 256 + j] = (vals[i] - mu) * inv * gamma[j] + beta[j];
    }
}

// ---------------------------------------------------------------------------
extern "C" void kernel_launch(void* const* d_in, const int* in_sizes, int n_in,
                              void* d_out, int out_size) {
    const float* x     = (const float*)d_in[0];
    const int*   ei    = (const int*)d_in[1];   // JAX x64 disabled -> int32
    const float* W0    = (const float*)d_in[2];
    const float* as0   = (const float*)d_in[3];
    const float* ad0   = (const float*)d_in[4];
    const float* b0    = (const float*)d_in[5];
    const float* W1    = (const float*)d_in[6];
    const float* as1   = (const float*)d_in[7];
    const float* ad1   = (const float*)d_in[8];
    const float* b1    = (const float*)d_in[9];
    const float* gamma = (const float*)d_in[10];
    const float* beta  = (const float*)d_in[11];
    float* out = (float*)d_out;
    const int* row = ei;
    const int* col = ei + EE;

    gemm_kernel<<<dim3(4, (NN + 63) / 64), 256>>>(x, W0, W1);
    att_init_kernel<<<(NN * HH + 255) / 256, 256>>>(as0, ad0, as1, ad1);
    zero_kernel<<<2048, 256>>>();
    edge_acc_kernel<0><<<(EE * 32 + 255) / 256, 256>>>(row, col);
    edge_acc_kernel<1><<<(EE * 32 + 255) / 256, 256>>>(row, col);
    finalize_kernel<<<(NN * 32 + 255) / 256, 256>>>(x, b0, b1, gamma, beta, out);
}

// round 9
// speedup vs baseline: 1.1180x; 1.1180x over previous
#include <cuda_runtime.h>
#include <cuda_bf16.h>

#define NN   50000
#define EE   800000
#define HH   8
#define CPHN 16
#define NEG  0.2f
#define EPSN 1e-5f

// Scratch (device globals; allocation-free rule)
__device__ __align__(16) float g_xw[NN * 256];   // [n][hop*128 + h*16 + c]
__device__ __align__(16) float g_att[NN * 32];   // [n][hop*16 + {as:0..7, ad:8..15}]
__device__ __align__(16) float g_s[NN * 16];     // softmax denominator partial (edges only)
__device__ __align__(16) float g_acc[NN * 256];  // unnormalized weighted sums (edges only)
__device__ __align__(16) int   g_cnt[NN];        // multiplicity of node id c in col[]

__device__ __forceinline__ float lrelu(float v) { return v > 0.f ? v : NEG * v; }

// ---------------------------------------------------------------------------
// 1) xw = x @ [W0 | W1]  -> g_xw [NN, 256]
// ---------------------------------------------------------------------------
__global__ __launch_bounds__(256) void gemm_kernel(const float* __restrict__ A,
                                                   const float* __restrict__ W0,
                                                   const float* __restrict__ W1) {
    __shared__ __align__(16) float As[16][72];
    __shared__ __align__(16) float Bs[16][72];
    const int bm = blockIdx.y * 64;
    const int bn = blockIdx.x * 64;                 // 0,64,128,192
    const float* W = (bn < 128) ? W0 : W1;
    const int wcol = bn & 127;
    const int tid = threadIdx.x;
    const int ty = tid >> 4, tx = tid & 15;

    float acc[4][4] = {};
    const int arow = tid >> 2, ak4 = (tid & 3) * 4; // A loader mapping
    const int bk = tid >> 4, bn4 = (tid & 15) * 4;  // B loader mapping

    for (int k0 = 0; k0 < 256; k0 += 16) {
        float4 av = make_float4(0.f, 0.f, 0.f, 0.f);
        const int grow = bm + arow;
        if (grow < NN) av = *(const float4*)&A[grow * 256 + k0 + ak4];
        As[ak4 + 0][arow] = av.x;
        As[ak4 + 1][arow] = av.y;
        As[ak4 + 2][arow] = av.z;
        As[ak4 + 3][arow] = av.w;
        *(float4*)&Bs[bk][bn4] = *(const float4*)&W[(k0 + bk) * 128 + wcol + bn4];
        __syncthreads();
#pragma unroll
        for (int k = 0; k < 16; k++) {
            float4 a4 = *(const float4*)&As[k][ty * 4];
            float4 b4 = *(const float4*)&Bs[k][tx * 4];
            float a[4] = {a4.x, a4.y, a4.z, a4.w};
            float b[4] = {b4.x, b4.y, b4.z, b4.w};
#pragma unroll
            for (int i = 0; i < 4; i++)
#pragma unroll
                for (int j = 0; j < 4; j++) acc[i][j] += a[i] * b[j];
        }
        __syncthreads();
    }
#pragma unroll
    for (int i = 0; i < 4; i++) {
        const int grow = bm + ty * 4 + i;
        if (grow < NN) {
            float4 v = make_float4(acc[i][0], acc[i][1], acc[i][2], acc[i][3]);
            *(float4*)&g_xw[grow * 256 + bn + tx * 4] = v;
        }
    }
}

// ---------------------------------------------------------------------------
// 2) per-(node,head): attention logit pieces a_s, a_d for both hops
// ---------------------------------------------------------------------------
__global__ __launch_bounds__(256) void att_init_kernel(const float* __restrict__ as0,
                                                       const float* __restrict__ ad0,
                                                       const float* __restrict__ as1,
                                                       const float* __restrict__ ad1) {
    int t = blockIdx.x * blockDim.x + threadIdx.x;
    if (t >= NN * HH) return;
    const int n = t >> 3, h = t & 7;
    const float* xw0 = &g_xw[n * 256 + h * CPHN];
    const float* xw1 = xw0 + 128;
    float s0 = 0.f, d0 = 0.f, s1 = 0.f, d1 = 0.f;
#pragma unroll
    for (int c = 0; c < CPHN; c++) {
        const float v0 = xw0[c], v1 = xw1[c];
        s0 += v0 * __ldg(&as0[h * CPHN + c]);
        d0 += v0 * __ldg(&ad0[h * CPHN + c]);
        s1 += v1 * __ldg(&as1[h * CPHN + c]);
        d1 += v1 * __ldg(&ad1[h * CPHN + c]);
    }
    g_att[n * 32 + h]      = s0;
    g_att[n * 32 + 8 + h]  = d0;
    g_att[n * 32 + 16 + h] = s1;
    g_att[n * 32 + 24 + h] = d1;
}

__global__ void zero_kernel() {
    const int idx = blockIdx.x * blockDim.x + threadIdx.x;
    const int stride = gridDim.x * blockDim.x;
    const float4 z = make_float4(0.f, 0.f, 0.f, 0.f);
    for (int i = idx; i < NN * 16 / 4; i += stride) ((float4*)g_s)[i] = z;
    for (int i = idx; i < NN * 256 / 4; i += stride) ((float4*)g_acc)[i] = z;
    for (int i = idx; i < NN; i += stride) g_cnt[i] = 0;
}

// histogram: multiplicity of node id c among col[] (drives hop-1 collapse)
__global__ __launch_bounds__(256) void hist_kernel(const int* __restrict__ col) {
    const int t = blockIdx.x * blockDim.x + threadIdx.x;
    if (t * 4 >= EE) return;
    const int4 c4 = ((const int4*)col)[t];
    atomicAdd(&g_cnt[c4.x], 1);
    atomicAdd(&g_cnt[c4.y], 1);
    atomicAdd(&g_cnt[c4.z], 1);
    atomicAdd(&g_cnt[c4.w], 1);
}

// ---------------------------------------------------------------------------
// 3a) hop-0 edge pass: warp per edge; lane j owns channels 4j..4j+3 (one head)
// ---------------------------------------------------------------------------
__global__ __launch_bounds__(256) void edge_acc0_kernel(const int* __restrict__ row,
                                                        const int* __restrict__ col) {
    const int w = (blockIdx.x * blockDim.x + threadIdx.x) >> 5;
    const int lane = threadIdx.x & 31;
    if (w >= EE) return;
    const int s = __ldg(&row[w]);
    const int d = __ldg(&col[w]);
    float p = 0.f;
    if (lane < 8) {
        const float as_ = g_att[s * 32 + lane];
        const float ad_ = g_att[d * 32 + 8 + lane];
        p = __expf(lrelu(as_ + ad_));
        atomicAdd(&g_s[d * 16 + lane], p);
    }
    const float pj = __shfl_sync(0xffffffffu, p, lane >> 2);   // head = (4*lane)>>4
    const float4 xv = ((const float4*)&g_xw[s * 256])[lane];
    float* ac = &g_acc[d * 256 + lane * 4];
    atomicAdd(&ac[0], pj * xv.x);
    atomicAdd(&ac[1], pj * xv.y);
    atomicAdd(&ac[2], pj * xv.z);
    atomicAdd(&ac[3], pj * xv.w);
}

// ---------------------------------------------------------------------------
// 3b) hop-1 edge pass, COLLAPSED: the reference's nr,nc = row[col], col[col]
// index the edge arrays by NODE ids (< NN), so hop-1's 800k edges are the
// first NN entries of (row,col), entry c with multiplicity cnt[c].
// Warp per c in [0, NN).
// ---------------------------------------------------------------------------
__global__ __launch_bounds__(256) void edge_acc1_kernel(const int* __restrict__ row,
                                                        const int* __restrict__ col) {
    const int c = (blockIdx.x * blockDim.x + threadIdx.x) >> 5;
    const int lane = threadIdx.x & 31;
    if (c >= NN) return;
    const int cnt = g_cnt[c];
    if (cnt == 0) return;
    const float wgt = (float)cnt;
    const int s = __ldg(&row[c]);
    const int d = __ldg(&col[c]);
    float p = 0.f;
    if (lane < 8) {
        const float as_ = g_att[s * 32 + 16 + lane];
        const float ad_ = g_att[d * 32 + 24 + lane];
        p = wgt * __expf(lrelu(as_ + ad_));
        atomicAdd(&g_s[d * 16 + 8 + lane], p);
    }
    const float pj = __shfl_sync(0xffffffffu, p, lane >> 2);
    const float4 xv = ((const float4*)&g_xw[s * 256 + 128])[lane];
    float* ac = &g_acc[d * 256 + 128 + lane * 4];
    atomicAdd(&ac[0], pj * xv.x);
    atomicAdd(&ac[1], pj * xv.y);
    atomicAdd(&ac[2], pj * xv.z);
    atomicAdd(&ac[3], pj * xv.w);
}

// ---------------------------------------------------------------------------
// 4) finalize: fold self loop(s), normalize, bias, residual, LayerNorm (warp/node)
//    Hop-2 self loops appear TWICE in the reference, so self term doubled there.
// ---------------------------------------------------------------------------
__global__ __launch_bounds__(256) void finalize_kernel(const float* __restrict__ x,
                                                       const float* __restrict__ b0,
                                                       const float* __restrict__ b1,
                                                       const float* __restrict__ gamma,
                                                       const float* __restrict__ beta,
                                                       float* __restrict__ out) {
    const int n = (blockIdx.x * blockDim.x + threadIdx.x) >> 5;
    const int lane = threadIdx.x & 31;
    if (n >= NN) return;
    float p = 0.f, stot = 1.f;
    if (lane < 16) {  // slot = hop*8 + h = lane
        const int hop = lane >> 3, h = lane & 7;
        const float as_ = g_att[n * 32 + hop * 16 + h];
        const float ad_ = g_att[n * 32 + hop * 16 + 8 + h];
        const float mult = (hop == 0) ? 1.f : 2.f;   // hop-2 self loop counted twice
        p = mult * __expf(lrelu(as_ + ad_));         // self-loop contribution
        stot = g_s[n * 16 + lane] + p;
    }
    float vals[8];
    float sum = 0.f, sumsq = 0.f;
#pragma unroll
    for (int i = 0; i < 8; i++) {
        const int j = lane + 32 * i;
        const int slot = j >> 4;  // = hop*8 + head
        const float pj = __shfl_sync(0xffffffffu, p, slot);
        const float sj = __shfl_sync(0xffffffffu, stot, slot);
        const float bias = (j < 128) ? __ldg(&b0[j]) : __ldg(&b1[j - 128]);
        const float v =
            (g_acc[n * 256 + j] + pj * g_xw[n * 256 + j]) / sj + bias + x[n * 256 + j];
        vals[i] = v;
        sum += v;
        sumsq += v * v;
    }
#pragma unroll
    for (int o = 16; o > 0; o >>= 1) {
        sum += __shfl_xor_sync(0xffffffffu, sum, o);
        sumsq += __shfl_xor_sync(0xffffffffu, sumsq, o);
    }
    const float mu = sum * (1.f / 256.f);
    const float var = sumsq * (1.f / 256.f) - mu * mu;
    const float inv = rsqrtf(var + EPSN);
#pragma unroll
    for (int i = 0; i < 8; i++) {
        const int j = lane + 32 * i;
        out[n * 256 + j] = (vals[i] - mu) * inv * gamma[j] + beta[j];
    }
}

// ---------------------------------------------------------------------------
extern "C" void kernel_launch(void* const* d_in, const int* in_sizes, int n_in,
                              void* d_out, int out_size) {
    const float* x     = (const float*)d_in[0];
    const int*   ei    = (const int*)d_in[1];   // JAX x64 disabled -> int32
    const float* W0    = (const float*)d_in[2];
    const float* as0   = (const float*)d_in[3];
    const float* ad0   = (const float*)d_in[4];
    const float* b0    = (const float*)d_in[5];
    const float* W1    = (const float*)d_in[6];
    const float* as1   = (const float*)d_in[7];
    const float* ad1   = (const float*)d_in[8];
    const float* b1    = (const float*)d_in[9];
    const float* gamma = (const float*)d_in[10];
    const float* beta  = (const float*)d_in[11];
    float* out = (float*)d_out;
    const int* row = ei;
    const int* col = ei + EE;

    gemm_kernel<<<dim3(4, (NN + 63) / 64), 256>>>(x, W0, W1);
    att_init_kernel<<<(NN * HH + 255) / 256, 256>>>(as0, ad0, as1, ad1);
    zero_kernel<<<2048, 256>>>();
    hist_kernel<<<(EE / 4 + 255) / 256, 256>>>(col);
    edge_acc0_kernel<<<(EE * 32 + 255) / 256, 256>>>(row, col);
    edge_acc1_kernel<<<(NN * 32 + 255) / 256, 256>>>(row, col);
    finalize_kernel<<<(NN * 32 + 255) / 256, 256>>>(x, b0, b1, gamma, beta, out);
}

// round 11
// speedup vs baseline: 1.4683x; 1.3133x over previous
#include <cuda_runtime.h>
#include <cuda_bf16.h>

#define NN   50000
#define EE   800000
#define HH   8
#define CPHN 16
#define NEG  0.2f
#define EPSN 1e-5f

// Scratch (device globals; allocation-free rule)
__device__ __align__(16) float g_xw[NN * 256];   // [n][hop*128 + h*16 + c]
__device__ __align__(16) float g_att[NN * 32];   // [n][hop*16 + {as:0..7, ad:8..15}]
__device__ __align__(16) float g_s[NN * 16];     // softmax denominators
__device__ __align__(16) float g_acc[NN * 256];  // unnormalized weighted sums
__device__ __align__(16) int   g_cnt[NN];        // in-degree of c in col[] (= hop-1 multiplicity)
__device__ __align__(16) int   g_off[NN];        // CSR offsets (ends after scatter)
__device__ __align__(16) int   g_src[EE];        // CSR-ordered src ids

__device__ __forceinline__ float lrelu(float v) { return v > 0.f ? v : NEG * v; }

// ---------------------------------------------------------------------------
// 1) xw = x @ [W0 | W1]  -> g_xw [NN, 256]
// ---------------------------------------------------------------------------
__global__ __launch_bounds__(256) void gemm_kernel(const float* __restrict__ A,
                                                   const float* __restrict__ W0,
                                                   const float* __restrict__ W1) {
    __shared__ __align__(16) float As[16][72];
    __shared__ __align__(16) float Bs[16][72];
    const int bm = blockIdx.y * 64;
    const int bn = blockIdx.x * 64;                 // 0,64,128,192
    const float* W = (bn < 128) ? W0 : W1;
    const int wcol = bn & 127;
    const int tid = threadIdx.x;
    const int ty = tid >> 4, tx = tid & 15;

    float acc[4][4] = {};
    const int arow = tid >> 2, ak4 = (tid & 3) * 4;
    const int bk = tid >> 4, bn4 = (tid & 15) * 4;

    for (int k0 = 0; k0 < 256; k0 += 16) {
        float4 av = make_float4(0.f, 0.f, 0.f, 0.f);
        const int grow = bm + arow;
        if (grow < NN) av = *(const float4*)&A[grow * 256 + k0 + ak4];
        As[ak4 + 0][arow] = av.x;
        As[ak4 + 1][arow] = av.y;
        As[ak4 + 2][arow] = av.z;
        As[ak4 + 3][arow] = av.w;
        *(float4*)&Bs[bk][bn4] = *(const float4*)&W[(k0 + bk) * 128 + wcol + bn4];
        __syncthreads();
#pragma unroll
        for (int k = 0; k < 16; k++) {
            float4 a4 = *(const float4*)&As[k][ty * 4];
            float4 b4 = *(const float4*)&Bs[k][tx * 4];
            float a[4] = {a4.x, a4.y, a4.z, a4.w};
            float b[4] = {b4.x, b4.y, b4.z, b4.w};
#pragma unroll
            for (int i = 0; i < 4; i++)
#pragma unroll
                for (int j = 0; j < 4; j++) acc[i][j] += a[i] * b[j];
        }
        __syncthreads();
    }
#pragma unroll
    for (int i = 0; i < 4; i++) {
        const int grow = bm + ty * 4 + i;
        if (grow < NN) {
            float4 v = make_float4(acc[i][0], acc[i][1], acc[i][2], acc[i][3]);
            *(float4*)&g_xw[grow * 256 + bn + tx * 4] = v;
        }
    }
}

// ---------------------------------------------------------------------------
// 2) per-(node,head): attention logit pieces a_s, a_d for both hops
// ---------------------------------------------------------------------------
__global__ __launch_bounds__(256) void att_init_kernel(const float* __restrict__ as0,
                                                       const float* __restrict__ ad0,
                                                       const float* __restrict__ as1,
                                                       const float* __restrict__ ad1) {
    int t = blockIdx.x * blockDim.x + threadIdx.x;
    if (t >= NN * HH) return;
    const int n = t >> 3, h = t & 7;
    const float* xw0 = &g_xw[n * 256 + h * CPHN];
    const float* xw1 = xw0 + 128;
    float s0 = 0.f, d0 = 0.f, s1 = 0.f, d1 = 0.f;
#pragma unroll
    for (int c = 0; c < CPHN; c++) {
        const float v0 = xw0[c], v1 = xw1[c];
        s0 += v0 * __ldg(&as0[h * CPHN + c]);
        d0 += v0 * __ldg(&ad0[h * CPHN + c]);
        s1 += v1 * __ldg(&as1[h * CPHN + c]);
        d1 += v1 * __ldg(&ad1[h * CPHN + c]);
    }
    g_att[n * 32 + h]      = s0;
    g_att[n * 32 + 8 + h]  = d0;
    g_att[n * 32 + 16 + h] = s1;
    g_att[n * 32 + 24 + h] = d1;
}

// zero only what hop-1 atomics need (+ histogram counters)
__global__ void zero_kernel() {
    const int idx = blockIdx.x * blockDim.x + threadIdx.x;
    const int stride = gridDim.x * blockDim.x;
    const float4 z = make_float4(0.f, 0.f, 0.f, 0.f);
    for (int i = idx; i < NN * 32; i += stride) {
        const int n = i >> 5, j = i & 31;
        ((float4*)&g_acc[n * 256 + 128])[j] = z;
    }
    for (int i = idx; i < NN * 2; i += stride) {
        const int n = i >> 1, j = i & 1;
        ((float4*)&g_s[n * 16 + 8])[j] = z;
    }
    for (int i = idx; i < NN; i += stride) g_cnt[i] = 0;
}

// histogram: in-degree over col[] (doubles as hop-1 multiplicity)
__global__ __launch_bounds__(256) void hist_kernel(const int* __restrict__ col) {
    const int t = blockIdx.x * blockDim.x + threadIdx.x;
    if (t * 4 >= EE) return;
    const int4 c4 = ((const int4*)col)[t];
    atomicAdd(&g_cnt[c4.x], 1);
    atomicAdd(&g_cnt[c4.y], 1);
    atomicAdd(&g_cnt[c4.z], 1);
    atomicAdd(&g_cnt[c4.w], 1);
}

// exclusive scan of g_cnt -> g_off (single block)
__global__ __launch_bounds__(1024) void scan_kernel() {
    __shared__ int wsum[32];
    const int t = threadIdx.x;
    const int CH = (NN + 1023) / 1024;  // 49
    const int b = t * CH;
    int sum = 0;
    for (int i = b; i < b + CH && i < NN; i++) sum += g_cnt[i];
    int v = sum;
#pragma unroll
    for (int o = 1; o < 32; o <<= 1) {
        const int nv = __shfl_up_sync(0xffffffffu, v, o);
        if ((t & 31) >= o) v += nv;
    }
    if ((t & 31) == 31) wsum[t >> 5] = v;
    __syncthreads();
    if (t < 32) {
        int w = wsum[t];
#pragma unroll
        for (int o = 1; o < 32; o <<= 1) {
            const int nw = __shfl_up_sync(0xffffffffu, w, o);
            if (t >= o) w += nw;
        }
        wsum[t] = w;
    }
    __syncthreads();
    int off = v - sum + ((t >= 32) ? wsum[(t >> 5) - 1] : 0);
    for (int i = b; i < b + CH && i < NN; i++) {
        g_off[i] = off;
        off += g_cnt[i];
    }
}

// scatter src ids into CSR order; afterwards g_off[c] = end offset of c
__global__ __launch_bounds__(256) void scatter_kernel(const int* __restrict__ row,
                                                      const int* __restrict__ col) {
    const int e = blockIdx.x * blockDim.x + threadIdx.x;
    if (e >= EE) return;
    const int d = __ldg(&col[e]);
    const int pos = atomicAdd(&g_off[d], 1);
    g_src[pos] = __ldg(&row[e]);
}

// ---------------------------------------------------------------------------
// 3a) hop-0, atomic-free: warp per dst node, register accumulation
// ---------------------------------------------------------------------------
__global__ __launch_bounds__(256) void csr_acc_kernel() {
    const int c = (blockIdx.x * blockDim.x + threadIdx.x) >> 5;
    const int lane = threadIdx.x & 31;
    if (c >= NN) return;
    const int start = (c > 0) ? g_off[c - 1] : 0;
    const int end = g_off[c];
    float ad_ = 0.f;
    if (lane < 8) ad_ = g_att[c * 32 + 8 + lane];
    float4 acc = make_float4(0.f, 0.f, 0.f, 0.f);
    float ps = 0.f;
    for (int e = start; e < end; e++) {
        const int s = __ldg(&g_src[e]);
        float p = 0.f;
        if (lane < 8) p = __expf(lrelu(g_att[s * 32 + lane] + ad_));
        ps += p;
        const float pj = __shfl_sync(0xffffffffu, p, lane >> 2);
        const float4 xv = ((const float4*)&g_xw[s * 256])[lane];
        acc.x += pj * xv.x;
        acc.y += pj * xv.y;
        acc.z += pj * xv.z;
        acc.w += pj * xv.w;
    }
    ((float4*)&g_acc[c * 256])[lane] = acc;
    if (lane < 8) g_s[c * 16 + lane] = ps;
}

// ---------------------------------------------------------------------------
// 3b) hop-1 (collapsed to NN weighted edges); coalesced-channel atomics
// ---------------------------------------------------------------------------
__global__ __launch_bounds__(256) void edge_acc1_kernel(const int* __restrict__ row,
                                                        const int* __restrict__ col) {
    const int c = (blockIdx.x * blockDim.x + threadIdx.x) >> 5;
    const int lane = threadIdx.x & 31;
    if (c >= NN) return;
    const int cnt = g_cnt[c];
    if (cnt == 0) return;
    const int s = __ldg(&row[c]);
    const int d = __ldg(&col[c]);
    float p = 0.f;
    if (lane < 8) {
        const float as_ = g_att[s * 32 + 16 + lane];
        const float ad_ = g_att[d * 32 + 24 + lane];
        p = (float)cnt * __expf(lrelu(as_ + ad_));
        atomicAdd(&g_s[d * 16 + 8 + lane], p);
    }
    const int h0 = lane >> 4;  // channel j=lane+32i -> head = h0 + 2i
    const float p0 = __shfl_sync(0xffffffffu, p, h0);
    const float p1 = __shfl_sync(0xffffffffu, p, h0 + 2);
    const float p2 = __shfl_sync(0xffffffffu, p, h0 + 4);
    const float p3 = __shfl_sync(0xffffffffu, p, h0 + 6);
    const float* xs = &g_xw[s * 256 + 128];
    float* ac = &g_acc[d * 256 + 128];
    atomicAdd(&ac[lane], p0 * xs[lane]);
    atomicAdd(&ac[lane + 32], p1 * xs[lane + 32]);
    atomicAdd(&ac[lane + 64], p2 * xs[lane + 64]);
    atomicAdd(&ac[lane + 96], p3 * xs[lane + 96]);
}

// ---------------------------------------------------------------------------
// 4) finalize: fold self loop(s), normalize, bias, residual, LayerNorm
// ---------------------------------------------------------------------------
__global__ __launch_bounds__(256) void finalize_kernel(const float* __restrict__ x,
                                                       const float* __restrict__ b0,
                                                       const float* __restrict__ b1,
                                                       const float* __restrict__ gamma,
                                                       const float* __restrict__ beta,
                                                       float* __restrict__ out) {
    const int n = (blockIdx.x * blockDim.x + threadIdx.x) >> 5;
    const int lane = threadIdx.x & 31;
    if (n >= NN) return;
    float p = 0.f, stot = 1.f;
    if (lane < 16) {  // slot = hop*8 + h = lane
        const int hop = lane >> 3, h = lane & 7;
        const float as_ = g_att[n * 32 + hop * 16 + h];
        const float ad_ = g_att[n * 32 + hop * 16 + 8 + h];
        const float mult = (hop == 0) ? 1.f : 2.f;   // hop-2 self loop counted twice
        p = mult * __expf(lrelu(as_ + ad_));
        stot = g_s[n * 16 + lane] + p;
    }
    float vals[8];
    float sum = 0.f, sumsq = 0.f;
#pragma unroll
    for (int i = 0; i < 8; i++) {
        const int j = lane + 32 * i;
        const int slot = j >> 4;  // = hop*8 + head
        const float pj = __shfl_sync(0xffffffffu, p, slot);
        const float sj = __shfl_sync(0xffffffffu, stot, slot);
        const float bias = (j < 128) ? __ldg(&b0[j]) : __ldg(&b1[j - 128]);
        const float v =
            (g_acc[n * 256 + j] + pj * g_xw[n * 256 + j]) / sj + bias + x[n * 256 + j];
        vals[i] = v;
        sum += v;
        sumsq += v * v;
    }
#pragma unroll
    for (int o = 16; o > 0; o >>= 1) {
        sum += __shfl_xor_sync(0xffffffffu, sum, o);
        sumsq += __shfl_xor_sync(0xffffffffu, sumsq, o);
    }
    const float mu = sum * (1.f / 256.f);
    const float var = sumsq * (1.f / 256.f) - mu * mu;
    const float inv = rsqrtf(var + EPSN);
#pragma unroll
    for (int i = 0; i < 8; i++) {
        const int j = lane + 32 * i;
        out[n * 256 + j] = (vals[i] - mu) * inv * gamma[j] + beta[j];
    }
}

// ---------------------------------------------------------------------------
extern "C" void kernel_launch(void* const* d_in, const int* in_sizes, int n_in,
                              void* d_out, int out_size) {
    const float* x     = (const float*)d_in[0];
    const int*   ei    = (const int*)d_in[1];   // JAX x64 disabled -> int32
    const float* W0    = (const float*)d_in[2];
    const float* as0   = (const float*)d_in[3];
    const float* ad0   = (const float*)d_in[4];
    const float* b0    = (const float*)d_in[5];
    const float* W1    = (const float*)d_in[6];
    const float* as1   = (const float*)d_in[7];
    const float* ad1   = (const float*)d_in[8];
    const float* b1    = (const float*)d_in[9];
    const float* gamma = (const float*)d_in[10];
    const float* beta  = (const float*)d_in[11];
    float* out = (float*)d_out;
    const int* row = ei;
    const int* col = ei + EE;

    gemm_kernel<<<dim3(4, (NN + 63) / 64), 256>>>(x, W0, W1);
    att_init_kernel<<<(NN * HH + 255) / 256, 256>>>(as0, ad0, as1, ad1);
    zero_kernel<<<2048, 256>>>();
    hist_kernel<<<(EE / 4 + 255) / 256, 256>>>(col);
    scan_kernel<<<1, 1024>>>();
    scatter_kernel<<<(EE + 255) / 256, 256>>>(row, col);
    csr_acc_kernel<<<(NN * 32 + 255) / 256, 256>>>();
    edge_acc1_kernel<<<(NN * 32 + 255) / 256, 256>>>(row, col);
    finalize_kernel<<<(NN * 32 + 255) / 256, 256>>>(x, b0, b1, gamma, beta, out);
}

// round 16
// speedup vs baseline: 1.9635x; 1.3373x over previous
#include <cuda_runtime.h>
#include <cuda_bf16.h>
#include <cstdint>

#define NN   50000
#define EE   800000
#define HH   8
#define CPHN 16
#define NEG  0.2f
#define EPSN 1e-5f

// Scratch (device globals; allocation-free rule)
__device__ __align__(16) float g_xw[NN * 256];   // [n][hop*128 + h*16 + c]
__device__ __align__(16) float g_att[NN * 32];   // [n][hop*16 + {as:0..7, ad:8..15}]
__device__ __align__(16) float g_s[NN * 16];     // softmax denominators
__device__ __align__(16) float g_acc[NN * 256];  // unnormalized weighted sums
__device__ __align__(16) int   g_cnt[NN];        // in-degree of c in col[] (= hop-1 multiplicity)
__device__ __align__(16) int   g_off[NN];        // CSR offsets (ends after scatter)
__device__ __align__(16) int   g_src[EE];        // CSR-ordered src ids
// W split hi/lo bf16, transposed: [half][kc][n(128)][kk(32) pad to 40]
#define BT_STRIDE 40
#define BT_TILE   (128 * BT_STRIDE)  // 5120 bf16 per (half,kc)
__device__ __align__(16) __nv_bfloat16 g_Bthi[2 * 8 * BT_TILE];
__device__ __align__(16) __nv_bfloat16 g_Btlo[2 * 8 * BT_TILE];

__device__ __forceinline__ float lrelu(float v) { return v > 0.f ? v : NEG * v; }

__device__ __forceinline__ void mma_bf16(float* d, const uint32_t* a, const uint32_t* b) {
    asm volatile(
        "mma.sync.aligned.m16n8k16.row.col.f32.bf16.bf16.f32 "
        "{%0,%1,%2,%3}, {%4,%5,%6,%7}, {%8,%9}, {%0,%1,%2,%3};"
        : "+f"(d[0]), "+f"(d[1]), "+f"(d[2]), "+f"(d[3])
        : "r"(a[0]), "r"(a[1]), "r"(a[2]), "r"(a[3]), "r"(b[0]), "r"(b[1]));
}

// ---------------------------------------------------------------------------
// 0) split W into hi/lo bf16, transposed to [n][k] tiles (once per launch)
// ---------------------------------------------------------------------------
__global__ __launch_bounds__(256) void bsw_kernel(const float* __restrict__ W0,
                                                  const float* __restrict__ W1) {
    const int t = blockIdx.x * blockDim.x + threadIdx.x;
    if (t >= 2 * 256 * 128) return;
    const int nh = t >> 15;
    const int k = (t & 32767) >> 7;  // 0..255
    const int n = t & 127;           // 0..127
    const float v = (nh ? W1 : W0)[k * 128 + n];
    const __nv_bfloat16 hi = __float2bfloat16(v);
    const __nv_bfloat16 lo = __float2bfloat16(v - __bfloat162float(hi));
    const int kc = k >> 5, kk = k & 31;
    const int dst = (nh * 8 + kc) * BT_TILE + n * BT_STRIDE + kk;
    g_Bthi[dst] = hi;
    g_Btlo[dst] = lo;
}

// ---------------------------------------------------------------------------
// 1) HMMA GEMM: g_xw[bm..+128][nh*128..+128] = x @ W(nh), bf16 hi/lo split
//    256 threads = 8 warps (4 m-rows x 2 n-cols), warp tile 32x64
// ---------------------------------------------------------------------------
__global__ __launch_bounds__(256) void mma_gemm_kernel(const float* __restrict__ x) {
    __shared__ __align__(16) __nv_bfloat16 AsHi[128 * BT_STRIDE];
    __shared__ __align__(16) __nv_bfloat16 AsLo[128 * BT_STRIDE];
    __shared__ __align__(16) __nv_bfloat16 BsHi[128 * BT_STRIDE];
    __shared__ __align__(16) __nv_bfloat16 BsLo[128 * BT_STRIDE];

    const int tid = threadIdx.x;
    const int wid = tid >> 5, lane = tid & 31;
    const int g = lane >> 2, tg = lane & 3;
    const int bm = blockIdx.y * 128;
    const int nh = blockIdx.x;
    const int warp_m = (wid & 3) * 32;
    const int warp_n = (wid >> 2) * 64;

    float acc[2][8][4] = {};

    for (int kc = 0; kc < 8; kc++) {
        __syncthreads();
        // fill A hi/lo: 128 rows x 32 k
        for (int i = 0; i < 4; i++) {
            const int idx = tid + i * 256;       // 0..1023 float4 slots
            const int m = idx >> 3, q = idx & 7; // q*4 = k offset
            const int gr = bm + m;
            float4 v = make_float4(0.f, 0.f, 0.f, 0.f);
            if (gr < NN) v = *(const float4*)&x[gr * 256 + kc * 32 + q * 4];
            const __nv_bfloat16 hx = __float2bfloat16(v.x), hy = __float2bfloat16(v.y);
            const __nv_bfloat16 hz = __float2bfloat16(v.z), hw = __float2bfloat16(v.w);
            __nv_bfloat162 h0, h1, l0, l1;
            h0.x = hx; h0.y = hy; h1.x = hz; h1.y = hw;
            l0.x = __float2bfloat16(v.x - __bfloat162float(hx));
            l0.y = __float2bfloat16(v.y - __bfloat162float(hy));
            l1.x = __float2bfloat16(v.z - __bfloat162float(hz));
            l1.y = __float2bfloat16(v.w - __bfloat162float(hw));
            const int o = m * BT_STRIDE + q * 4;
            *(__nv_bfloat162*)&AsHi[o] = h0;
            *(__nv_bfloat162*)&AsHi[o + 2] = h1;
            *(__nv_bfloat162*)&AsLo[o] = l0;
            *(__nv_bfloat162*)&AsLo[o + 2] = l1;
        }
        // fill B hi/lo: linear copy of pre-transposed tile (10240 B each)
        {
            const float4* sh = (const float4*)&g_Bthi[(nh * 8 + kc) * BT_TILE];
            const float4* sl = (const float4*)&g_Btlo[(nh * 8 + kc) * BT_TILE];
            float4* dh = (float4*)BsHi;
            float4* dl = (float4*)BsLo;
            for (int i = tid; i < BT_TILE / 8; i += 256) {  // 640 float4
                dh[i] = sh[i];
                dl[i] = sl[i];
            }
        }
        __syncthreads();

#pragma unroll
        for (int ks = 0; ks < 2; ks++) {
            const int kb = ks * 16;
            uint32_t ah[2][4], al[2][4];
#pragma unroll
            for (int mt = 0; mt < 2; mt++) {
                const int r0 = warp_m + mt * 16 + g;
                const int c0 = kb + 2 * tg;
                ah[mt][0] = *(const uint32_t*)&AsHi[r0 * BT_STRIDE + c0];
                ah[mt][1] = *(const uint32_t*)&AsHi[(r0 + 8) * BT_STRIDE + c0];
                ah[mt][2] = *(const uint32_t*)&AsHi[r0 * BT_STRIDE + c0 + 8];
                ah[mt][3] = *(const uint32_t*)&AsHi[(r0 + 8) * BT_STRIDE + c0 + 8];
                al[mt][0] = *(const uint32_t*)&AsLo[r0 * BT_STRIDE + c0];
                al[mt][1] = *(const uint32_t*)&AsLo[(r0 + 8) * BT_STRIDE + c0];
                al[mt][2] = *(const uint32_t*)&AsLo[r0 * BT_STRIDE + c0 + 8];
                al[mt][3] = *(const uint32_t*)&AsLo[(r0 + 8) * BT_STRIDE + c0 + 8];
            }
#pragma unroll
            for (int nt = 0; nt < 8; nt++) {
                const int nr = warp_n + nt * 8 + g;
                const int c0 = kb + 2 * tg;
                uint32_t bh[2], bl[2];
                bh[0] = *(const uint32_t*)&BsHi[nr * BT_STRIDE + c0];
                bh[1] = *(const uint32_t*)&BsHi[nr * BT_STRIDE + c0 + 8];
                bl[0] = *(const uint32_t*)&BsLo[nr * BT_STRIDE + c0];
                bl[1] = *(const uint32_t*)&BsLo[nr * BT_STRIDE + c0 + 8];
#pragma unroll
                for (int mt = 0; mt < 2; mt++) {
                    mma_bf16(acc[mt][nt], ah[mt], bh);
                    mma_bf16(acc[mt][nt], ah[mt], bl);
                    mma_bf16(acc[mt][nt], al[mt], bh);
                }
            }
        }
    }

    // epilogue: fragment -> global (float2 stores)
#pragma unroll
    for (int mt = 0; mt < 2; mt++) {
#pragma unroll
        for (int nt = 0; nt < 8; nt++) {
            const int cidx = nh * 128 + warp_n + nt * 8 + 2 * tg;
            const int r0 = bm + warp_m + mt * 16 + g;
            if (r0 < NN) {
                float2 v0 = make_float2(acc[mt][nt][0], acc[mt][nt][1]);
                *(float2*)&g_xw[r0 * 256 + cidx] = v0;
            }
            const int r1 = r0 + 8;
            if (r1 < NN) {
                float2 v1 = make_float2(acc[mt][nt][2], acc[mt][nt][3]);
                *(float2*)&g_xw[r1 * 256 + cidx] = v1;
            }
        }
    }
}

// ---------------------------------------------------------------------------
// 2) per-(node,head): attention logit pieces a_s, a_d for both hops
// ---------------------------------------------------------------------------
__global__ __launch_bounds__(256) void att_init_kernel(const float* __restrict__ as0,
                                                       const float* __restrict__ ad0,
                                                       const float* __restrict__ as1,
                                                       const float* __restrict__ ad1) {
    int t = blockIdx.x * blockDim.x + threadIdx.x;
    if (t >= NN * HH) return;
    const int n = t >> 3, h = t & 7;
    const float* xw0 = &g_xw[n * 256 + h * CPHN];
    const float* xw1 = xw0 + 128;
    float s0 = 0.f, d0 = 0.f, s1 = 0.f, d1 = 0.f;
#pragma unroll
    for (int c = 0; c < CPHN; c++) {
        const float v0 = xw0[c], v1 = xw1[c];
        s0 += v0 * __ldg(&as0[h * CPHN + c]);
        d0 += v0 * __ldg(&ad0[h * CPHN + c]);
        s1 += v1 * __ldg(&as1[h * CPHN + c]);
        d1 += v1 * __ldg(&ad1[h * CPHN + c]);
    }
    g_att[n * 32 + h]      = s0;
    g_att[n * 32 + 8 + h]  = d0;
    g_att[n * 32 + 16 + h] = s1;
    g_att[n * 32 + 24 + h] = d1;
}

// zero only what hop-1 atomics need (+ histogram counters)
__global__ void zero_kernel() {
    const int idx = blockIdx.x * blockDim.x + threadIdx.x;
    const int stride = gridDim.x * blockDim.x;
    const float4 z = make_float4(0.f, 0.f, 0.f, 0.f);
    for (int i = idx; i < NN * 32; i += stride) {
        const int n = i >> 5, j = i & 31;
        ((float4*)&g_acc[n * 256 + 128])[j] = z;
    }
    for (int i = idx; i < NN * 2; i += stride) {
        const int n = i >> 1, j = i & 1;
        ((float4*)&g_s[n * 16 + 8])[j] = z;
    }
    for (int i = idx; i < NN; i += stride) g_cnt[i] = 0;
}

// histogram: in-degree over col[] (doubles as hop-1 multiplicity)
__global__ __launch_bounds__(256) void hist_kernel(const int* __restrict__ col) {
    const int t = blockIdx.x * blockDim.x + threadIdx.x;
    if (t * 4 >= EE) return;
    const int4 c4 = ((const int4*)col)[t];
    atomicAdd(&g_cnt[c4.x], 1);
    atomicAdd(&g_cnt[c4.y], 1);
    atomicAdd(&g_cnt[c4.z], 1);
    atomicAdd(&g_cnt[c4.w], 1);
}

// exclusive scan of g_cnt -> g_off (single block)
__global__ __launch_bounds__(1024) void scan_kernel() {
    __shared__ int wsum[32];
    const int t = threadIdx.x;
    const int CH = (NN + 1023) / 1024;  // 49
    const int b = t * CH;
    int sum = 0;
    for (int i = b; i < b + CH && i < NN; i++) sum += g_cnt[i];
    int v = sum;
#pragma unroll
    for (int o = 1; o < 32; o <<= 1) {
        const int nv = __shfl_up_sync(0xffffffffu, v, o);
        if ((t & 31) >= o) v += nv;
    }
    if ((t & 31) == 31) wsum[t >> 5] = v;
    __syncthreads();
    if (t < 32) {
        int w = wsum[t];
#pragma unroll
        for (int o = 1; o < 32; o <<= 1) {
            const int nw = __shfl_up_sync(0xffffffffu, w, o);
            if (t >= o) w += nw;
        }
        wsum[t] = w;
    }
    __syncthreads();
    int off = v - sum + ((t >= 32) ? wsum[(t >> 5) - 1] : 0);
    for (int i = b; i < b + CH && i < NN; i++) {
        g_off[i] = off;
        off += g_cnt[i];
    }
}

// scatter src ids into CSR order; afterwards g_off[c] = end offset of c
__global__ __launch_bounds__(256) void scatter_kernel(const int* __restrict__ row,
                                                      const int* __restrict__ col) {
    const int e = blockIdx.x * blockDim.x + threadIdx.x;
    if (e >= EE) return;
    const int d = __ldg(&col[e]);
    const int pos = atomicAdd(&g_off[d], 1);
    g_src[pos] = __ldg(&row[e]);
}

// ---------------------------------------------------------------------------
// 3a) hop-0, atomic-free: warp per dst node, register accumulation
// ---------------------------------------------------------------------------
__global__ __launch_bounds__(256) void csr_acc_kernel() {
    const int c = (blockIdx.x * blockDim.x + threadIdx.x) >> 5;
    const int lane = threadIdx.x & 31;
    if (c >= NN) return;
    const int start = (c > 0) ? g_off[c - 1] : 0;
    const int end = g_off[c];
    float ad_ = 0.f;
    if (lane < 8) ad_ = g_att[c * 32 + 8 + lane];
    float4 acc = make_float4(0.f, 0.f, 0.f, 0.f);
    float ps = 0.f;
    for (int e = start; e < end; e++) {
        const int s = __ldg(&g_src[e]);
        float p = 0.f;
        if (lane < 8) p = __expf(lrelu(g_att[s * 32 + lane] + ad_));
        ps += p;
        const float pj = __shfl_sync(0xffffffffu, p, lane >> 2);
        const float4 xv = ((const float4*)&g_xw[s * 256])[lane];
        acc.x += pj * xv.x;
        acc.y += pj * xv.y;
        acc.z += pj * xv.z;
        acc.w += pj * xv.w;
    }
    ((float4*)&g_acc[c * 256])[lane] = acc;
    if (lane < 8) g_s[c * 16 + lane] = ps;
}

// ---------------------------------------------------------------------------
// 3b) hop-1 (collapsed to NN weighted edges); coalesced-channel atomics
// ---------------------------------------------------------------------------
__global__ __launch_bounds__(256) void edge_acc1_kernel(const int* __restrict__ row,
                                                        const int* __restrict__ col) {
    const int c = (blockIdx.x * blockDim.x + threadIdx.x) >> 5;
    const int lane = threadIdx.x & 31;
    if (c >= NN) return;
    const int cnt = g_cnt[c];
    if (cnt == 0) return;
    const int s = __ldg(&row[c]);
    const int d = __ldg(&col[c]);
    float p = 0.f;
    if (lane < 8) {
        const float as_ = g_att[s * 32 + 16 + lane];
        const float ad_ = g_att[d * 32 + 24 + lane];
        p = (float)cnt * __expf(lrelu(as_ + ad_));
        atomicAdd(&g_s[d * 16 + 8 + lane], p);
    }
    const int h0 = lane >> 4;  // channel j=lane+32i -> head = h0 + 2i
    const float p0 = __shfl_sync(0xffffffffu, p, h0);
    const float p1 = __shfl_sync(0xffffffffu, p, h0 + 2);
    const float p2 = __shfl_sync(0xffffffffu, p, h0 + 4);
    const float p3 = __shfl_sync(0xffffffffu, p, h0 + 6);
    const float* xs = &g_xw[s * 256 + 128];
    float* ac = &g_acc[d * 256 + 128];
    atomicAdd(&ac[lane], p0 * xs[lane]);
    atomicAdd(&ac[lane + 32], p1 * xs[lane + 32]);
    atomicAdd(&ac[lane + 64], p2 * xs[lane + 64]);
    atomicAdd(&ac[lane + 96], p3 * xs[lane + 96]);
}

// ---------------------------------------------------------------------------
// 4) finalize: fold self loop(s), normalize, bias, residual, LayerNorm
// ---------------------------------------------------------------------------
__global__ __launch_bounds__(256) void finalize_kernel(const float* __restrict__ x,
                                                       const float* __restrict__ b0,
                                                       const float* __restrict__ b1,
                                                       const float* __restrict__ gamma,
                                                       const float* __restrict__ beta,
                                                       float* __restrict__ out) {
    const int n = (blockIdx.x * blockDim.x + threadIdx.x) >> 5;
    const int lane = threadIdx.x & 31;
    if (n >= NN) return;
    float p = 0.f, stot = 1.f;
    if (lane < 16) {  // slot = hop*8 + h = lane
        const int hop = lane >> 3, h = lane & 7;
        const float as_ = g_att[n * 32 + hop * 16 + h];
        const float ad_ = g_att[n * 32 + hop * 16 + 8 + h];
        const float mult = (hop == 0) ? 1.f : 2.f;   // hop-2 self loop counted twice
        p = mult * __expf(lrelu(as_ + ad_));
        stot = g_s[n * 16 + lane] + p;
    }
    float vals[8];
    float sum = 0.f, sumsq = 0.f;
#pragma unroll
    for (int i = 0; i < 8; i++) {
        const int j = lane + 32 * i;
        const int slot = j >> 4;  // = hop*8 + head
        const float pj = __shfl_sync(0xffffffffu, p, slot);
        const float sj = __shfl_sync(0xffffffffu, stot, slot);
        const float bias = (j < 128) ? __ldg(&b0[j]) : __ldg(&b1[j - 128]);
        const float v =
            (g_acc[n * 256 + j] + pj * g_xw[n * 256 + j]) / sj + bias + x[n * 256 + j];
        vals[i] = v;
        sum += v;
        sumsq += v * v;
    }
#pragma unroll
    for (int o = 16; o > 0; o >>= 1) {
        sum += __shfl_xor_sync(0xffffffffu, sum, o);
        sumsq += __shfl_xor_sync(0xffffffffu, sumsq, o);
    }
    const float mu = sum * (1.f / 256.f);
    const float var = sumsq * (1.f / 256.f) - mu * mu;
    const float inv = rsqrtf(var + EPSN);
#pragma unroll
    for (int i = 0; i < 8; i++) {
        const int j = lane + 32 * i;
        out[n * 256 + j] = (vals[i] - mu) * inv * gamma[j] + beta[j];
    }
}

// ---------------------------------------------------------------------------
extern "C" void kernel_launch(void* const* d_in, const int* in_sizes, int n_in,
                              void* d_out, int out_size) {
    const float* x     = (const float*)d_in[0];
    const int*   ei    = (const int*)d_in[1];   // JAX x64 disabled -> int32
    const float* W0    = (const float*)d_in[2];
    const float* as0   = (const float*)d_in[3];
    const float* ad0   = (const float*)d_in[4];
    const float* b0    = (const float*)d_in[5];
    const float* W1    = (const float*)d_in[6];
    const float* as1   = (const float*)d_in[7];
    const float* ad1   = (const float*)d_in[8];
    const float* b1    = (const float*)d_in[9];
    const float* gamma = (const float*)d_in[10];
    const float* beta  = (const float*)d_in[11];
    float* out = (float*)d_out;
    const int* row = ei;
    const int* col = ei + EE;

    bsw_kernel<<<(2 * 256 * 128 + 255) / 256, 256>>>(W0, W1);
    mma_gemm_kernel<<<dim3(2, (NN + 127) / 128), 256>>>(x);
    att_init_kernel<<<(NN * HH + 255) / 256, 256>>>(as0, ad0, as1, ad1);
    zero_kernel<<<2048, 256>>>();
    hist_kernel<<<(EE / 4 + 255) / 256, 256>>>(col);
    scan_kernel<<<1, 1024>>>();
    scatter_kernel<<<(EE + 255) / 256, 256>>>(row, col);
    csr_acc_kernel<<<(NN * 32 + 255) / 256, 256>>>();
    edge_acc1_kernel<<<(NN * 32 + 255) / 256, 256>>>(row, col);
    finalize_kernel<<<(NN * 32 + 255) / 256, 256>>>(x, b0, b1, gamma, beta, out);
}